// round 8
// baseline (speedup 1.0000x reference)
#include <cuda_runtime.h>
#include <cuda_bf16.h>
#include <math.h>
#include <stdint.h>

#define Nn   4096
#define Bb   2048
#define DIM  128
#define NT   32
#define NTILES 528
#define GRID2 132                       // 132 CTAs x exactly 4 tiles
#define EPSV 1e-8f
#define INV_T 14.285714285714285714f   // 1/0.07
#define LOG2E 1.44269504088896340736f

// ---------------- static device scratch ----------------
__device__ __nv_bfloat16 g_zh[Nn * DIM];          // 1 MB hi split
__device__ __nv_bfloat16 g_zl[Nn * DIM];          // 1 MB lo split
__device__ float         g_simu[(size_t)NTILES * 16384]; // 34.6 MB upper-tri tiles
__device__ float         g_pdr[3][NT][Nn];        // row-side partials (slot = bx)
__device__ float         g_pdc[3][NT][Nn];        // col-side partials (slot = by)
__device__ float         g_row[Nn];
__device__ float         g_inv_dymax;
__device__ unsigned      g_min_key;

// panel layout in dynamic smem (bf16, 128 rows x 136 stride = 272 B/row)
#define PSTRIDE_B 272
#define OFF_A_H   0
#define OFF_A_L   34816
#define OFF_B0_H  69632
#define OFF_B0_L  104448
#define OFF_B1_H  139264
#define OFF_B1_L  174080
#define PANEL_BYTES 208896

__device__ __forceinline__ unsigned fflip(float f) {
    unsigned u = __float_as_uint(f);
    return (u & 0x80000000u) ? ~u : (u | 0x80000000u);
}
__device__ __forceinline__ float funflip(unsigned k) {
    return __uint_as_float((k & 0x80000000u) ? (k & 0x7FFFFFFFu) : ~k);
}
__device__ __forceinline__ uint32_t smem_u32(const void* p) {
    uint32_t a;
    asm("{ .reg .u64 t; cvta.to.shared.u64 t, %1; cvt.u32.u64 %0, t; }" : "=r"(a) : "l"(p));
    return a;
}
__device__ __forceinline__ void cp16(uint32_t s, const void* g) {
    asm volatile("cp.async.cg.shared.global [%0], [%1], 16;" :: "r"(s), "l"(g));
}
__device__ __forceinline__ void cp_commit() {
    asm volatile("cp.async.commit_group;");
}
template <int N> __device__ __forceinline__ void cp_wait() {
    asm volatile("cp.async.wait_group %0;" :: "n"(N));
}
__device__ __forceinline__ void ldsm4(uint32_t& r0, uint32_t& r1, uint32_t& r2, uint32_t& r3, uint32_t a) {
    asm volatile("ldmatrix.sync.aligned.m8n8.x4.shared.b16 {%0,%1,%2,%3}, [%4];"
                 : "=r"(r0), "=r"(r1), "=r"(r2), "=r"(r3) : "r"(a));
}
__device__ __forceinline__ void mma16816(float* c, const uint32_t* a, const uint32_t* b) {
    asm volatile("mma.sync.aligned.m16n8k16.row.col.f32.bf16.bf16.f32 "
                 "{%0,%1,%2,%3},{%4,%5,%6,%7},{%8,%9},{%0,%1,%2,%3};"
                 : "+f"(c[0]), "+f"(c[1]), "+f"(c[2]), "+f"(c[3])
                 : "r"(a[0]), "r"(a[1]), "r"(a[2]), "r"(a[3]), "r"(b[0]), "r"(b[1]));
}

// ---------------- kernel 1: labels min/max + init ----------------
__global__ void labels_kernel(const float* __restrict__ labels) {
    __shared__ float smn[32], smx[32];
    int tid = threadIdx.x;
    float mn = 1e30f, mx = -1e30f;
    for (int i = tid; i < Bb; i += 1024) {
        float v = labels[i];
        mn = fminf(mn, v); mx = fmaxf(mx, v);
    }
    #pragma unroll
    for (int off = 16; off; off >>= 1) {
        mn = fminf(mn, __shfl_xor_sync(0xffffffffu, mn, off));
        mx = fmaxf(mx, __shfl_xor_sync(0xffffffffu, mx, off));
    }
    int lane = tid & 31, w = tid >> 5;
    if (lane == 0) { smn[w] = mn; smx[w] = mx; }
    __syncthreads();
    if (tid == 0) {
        float a = smn[0], b = smx[0];
        for (int i = 1; i < 32; i++) { a = fminf(a, smn[i]); b = fmaxf(b, smx[i]); }
        g_inv_dymax = 1.0f / ((b - a) + EPSV);
        g_min_key   = 0xFFFFFFFFu;
    }
}

// ---------------- kernel 2: normalize + bf16 split ----------------
__global__ void normalize_kernel(const float* __restrict__ feats) {
    int gw   = (blockIdx.x * blockDim.x + threadIdx.x) >> 5;
    int lane = threadIdx.x & 31;
    if (gw >= Nn) return;
    int b = gw & (Bb - 1);
    int v = gw >> 11;
    const float* src = feats + ((size_t)b * 2 + v) * DIM;
    float4 x = *(const float4*)(src + lane * 4);
    float s = x.x * x.x + x.y * x.y + x.z * x.z + x.w * x.w;
    #pragma unroll
    for (int off = 16; off; off >>= 1) s += __shfl_xor_sync(0xffffffffu, s, off);
    float inv = 1.0f / fmaxf(sqrtf(s), 1e-12f);
    float f0 = x.x * inv, f1 = x.y * inv, f2 = x.z * inv, f3 = x.w * inv;
    __nv_bfloat16 h0 = __float2bfloat16(f0), h1 = __float2bfloat16(f1);
    __nv_bfloat16 h2 = __float2bfloat16(f2), h3 = __float2bfloat16(f3);
    __nv_bfloat16 l0 = __float2bfloat16(f0 - __bfloat162float(h0));
    __nv_bfloat16 l1 = __float2bfloat16(f1 - __bfloat162float(h1));
    __nv_bfloat16 l2 = __float2bfloat16(f2 - __bfloat162float(h2));
    __nv_bfloat16 l3 = __float2bfloat16(f3 - __bfloat162float(h3));
    size_t base = (size_t)gw * DIM + lane * 4;
    *(__nv_bfloat162*)(g_zh + base)     = __halves2bfloat162(h0, h1);
    *(__nv_bfloat162*)(g_zh + base + 2) = __halves2bfloat162(h2, h3);
    *(__nv_bfloat162*)(g_zl + base)     = __halves2bfloat162(l0, l1);
    *(__nv_bfloat162*)(g_zl + base + 2) = __halves2bfloat162(l2, l3);
}

// ---- cp.async panel loaders (H+L pair for one 128-row block), 512 threads --
__device__ __forceinline__ void load_panels(uint32_t sb, uint32_t offH, uint32_t offL,
                                            int blk, int tid) {
    #pragma unroll
    for (int c = tid; c < 2048; c += 512) {
        int row = c >> 4, ch = c & 15;
        uint32_t so = (uint32_t)row * PSTRIDE_B + ch * 16;
        size_t go = (size_t)(blk * 128 + row) * DIM + ch * 8;
        cp16(sb + offH + so, g_zh + go);
        cp16(sb + offL + so, g_zl + go);
    }
}

// ---- MMA on current buffers (16 warps, 32x32 outputs each) ----
__device__ __forceinline__ void tile_mma(uint32_t sb, uint32_t offBH, uint32_t offBL,
                                         int wm, int wn, int lane, float c[2][4][4]) {
    #pragma unroll
    for (int im = 0; im < 2; im++)
        #pragma unroll
        for (int in = 0; in < 4; in++)
            #pragma unroll
            for (int r = 0; r < 4; r++) c[im][in][r] = 0.0f;

    int a_row  = lane & 15;
    int a_koff = (lane >> 4) * 8;
    int b_row  = ((lane >> 4) & 1) * 8 + (lane & 7);
    int b_koff = ((lane >> 3) & 1) * 8;

    #pragma unroll
    for (int kc = 0; kc < 8; kc++) {
        uint32_t ah[2][4], al[2][4], bh[4][2], bl[4][2];
        #pragma unroll
        for (int im = 0; im < 2; im++) {
            uint32_t off = (uint32_t)(wm * 32 + im * 16 + a_row) * PSTRIDE_B
                         + (kc * 16 + a_koff) * 2;
            ldsm4(ah[im][0], ah[im][1], ah[im][2], ah[im][3], sb + OFF_A_H + off);
            ldsm4(al[im][0], al[im][1], al[im][2], al[im][3], sb + OFF_A_L + off);
        }
        #pragma unroll
        for (int p = 0; p < 2; p++) {
            uint32_t off = (uint32_t)(wn * 32 + p * 16 + b_row) * PSTRIDE_B
                         + (kc * 16 + b_koff) * 2;
            ldsm4(bh[2*p][0], bh[2*p][1], bh[2*p+1][0], bh[2*p+1][1], sb + offBH + off);
            ldsm4(bl[2*p][0], bl[2*p][1], bl[2*p+1][0], bl[2*p+1][1], sb + offBL + off);
        }
        #pragma unroll
        for (int im = 0; im < 2; im++)
            #pragma unroll
            for (int in = 0; in < 4; in++) {
                mma16816(c[im][in], ah[im], bh[in]);
                mma16816(c[im][in], ah[im], bl[in]);
                mma16816(c[im][in], al[im], bh[in]);
            }
    }
}

// ---------------- kernel 3: persistent pipelined GEMM (132 x 4 tiles) -------
__global__ void __launch_bounds__(512, 1) simgen_kernel() {
    extern __shared__ char sm[];
    __shared__ float wmin[16];
    uint32_t sb = smem_u32(sm);
    int tid = threadIdx.x, wid = tid >> 5, lane = tid & 31;
    int wm = wid & 3, wn = wid >> 2;
    int tr = lane >> 2, tq = (lane & 3) * 2;

    int ts = blockIdx.x * 4;
    int te = ts + 4;

    int by = 0, off = 0;
    while (ts >= off + (NT - by)) { off += (NT - by); by++; }
    int bx = by + (ts - off);

    float mymin = 1e30f;
    int t = ts;
    while (t < te) {
        int nb = NT - bx;
        if (nb > te - t) nb = te - t;

        load_panels(sb, OFF_A_H, OFF_A_L, by, tid);
        load_panels(sb, OFF_B0_H, OFF_B0_L, bx, tid);
        cp_commit();

        for (int j = 0; j < nb; j++) {
            uint32_t bH = (j & 1) ? OFF_B1_H : OFF_B0_H;
            uint32_t bL = (j & 1) ? OFF_B1_L : OFF_B0_L;
            if (j + 1 < nb) {
                load_panels(sb, (j & 1) ? OFF_B0_H : OFF_B1_H,
                                (j & 1) ? OFF_B0_L : OFF_B1_L, bx + j + 1, tid);
                cp_commit();
                cp_wait<1>();
            } else {
                cp_wait<0>();
            }
            __syncthreads();

            float c[2][4][4];
            tile_mma(sb, bH, bL, wm, wn, lane, c);

            float* dst = g_simu + (size_t)(t + j) * 16384;
            #pragma unroll
            for (int im = 0; im < 2; im++)
                #pragma unroll
                for (int in = 0; in < 4; in++) {
                    int rl = wm * 32 + im * 16 + tr;
                    int cl = wn * 32 + in * 8 + tq;
                    float2 v0 = make_float2(c[im][in][0], c[im][in][1]);
                    float2 v1 = make_float2(c[im][in][2], c[im][in][3]);
                    *(float2*)(dst + rl * 128 + cl)       = v0;
                    *(float2*)(dst + (rl + 8) * 128 + cl) = v1;
                    mymin = fminf(mymin, fminf(fminf(v0.x, v0.y), fminf(v1.x, v1.y)));
                }
            __syncthreads();
        }
        t += nb;
        bx += nb;
        if (bx >= NT) { by++; bx = by; }
    }

    #pragma unroll
    for (int o = 16; o; o >>= 1) mymin = fminf(mymin, __shfl_xor_sync(0xffffffffu, mymin, o));
    if (lane == 0) wmin[wid] = mymin;
    __syncthreads();
    if (tid == 0) {
        float m = wmin[0];
        #pragma unroll
        for (int w = 1; w < 16; w++) m = fminf(m, wmin[w]);
        atomicMin(&g_min_key, fflip(m));
    }
}

// ---------------- kernel 4: flat dual-sided epilogue ----------------
// 512 threads; warp handles 2 rows x 128 cols per iteration (rh = lane>>4).
__global__ void __launch_bounds__(512) epiflat_kernel(const float* __restrict__ labels) {
    __shared__ float yr[128], yc[128];
    __shared__ float rowacc[3][128];
    __shared__ float colacc[16][3][128];
    int tid = threadIdx.x, w = tid >> 5, lane = tid & 31;
    int rh = lane >> 4, cl = lane & 15;

    int t = blockIdx.x;
    int by = 0, off = 0;
    while (t >= off + (NT - by)) { off += (NT - by); by++; }
    int bx = by + (t - off);
    bool diag = (by == bx);

    for (int i = tid; i < 128; i += 512) {
        yr[i] = labels[(by * 128 + i) & (Bb - 1)];
        yc[i] = labels[(bx * 128 + i) & (Bb - 1)];
    }
    __syncthreads();

    float inv_dz = 1.0f / ((1.0f - funflip(g_min_key)) + EPSV);
    float inv_dy = g_inv_dymax;
    const float K1 = INV_T * LOG2E;        // exp(s/T) = exp2(s*K1)
    const float K2 = -2.0f * LOG2E;        // exp(-2dy^2) = exp2(dy*dy*K2)
    const float4* tp = (const float4*)(g_simu + (size_t)t * 16384);

    float yj[8];
    #pragma unroll
    for (int e = 0; e < 8; e++) yj[e] = yc[cl * 8 + e];

    float cd[8], c1v[8], c2v[8];
    #pragma unroll
    for (int e = 0; e < 8; e++) { cd[e] = 0.0f; c1v[e] = 0.0f; c2v[e] = 0.0f; }

    #pragma unroll
    for (int it = 0; it < 4; it++) {
        int row = it * 32 + w * 2 + rh;
        float4 sa = tp[row * 32 + cl * 2];
        float4 sb = tp[row * 32 + cl * 2 + 1];
        float se[8] = {sa.x, sa.y, sa.z, sa.w, sb.x, sb.y, sb.z, sb.w};
        float yi = yr[row];
        float rd = 0.0f, r1 = 0.0f, r2 = 0.0f;

        if (!diag) {
            #pragma unroll
            for (int e = 0; e < 8; e++) {
                float s   = se[e];
                float es  = exp2f(s * K1);
                float dy  = yi - yj[e];
                float wk  = exp2f(dy * (dy * K2));
                float u   = fmaf(-s, inv_dz, fmaf(-fabsf(dy), inv_dy, inv_dz));
                float wh  = fmaf(wk, u, 1.0f + fmaxf(-u, 0.0f));
                float wh2 = wh * wh;
                rd += es; r1 += wh; r2 = fmaf(wh2, s, r2);
                cd[e] += es; c1v[e] += wh; c2v[e] = fmaf(wh2, s, c2v[e]);
            }
        } else {
            #pragma unroll
            for (int e = 0; e < 8; e++) {
                float s   = se[e];
                float es  = exp2f(s * K1);
                float dy  = yi - yj[e];
                float wk  = exp2f(dy * (dy * K2));
                float u   = fmaf(-s, inv_dz, fmaf(-fabsf(dy), inv_dy, inv_dz));
                float wh  = fmaf(wk, u, 1.0f + fmaxf(-u, 0.0f));
                if (row == cl * 8 + e) { es = 0.0f; wh = 0.0f; }
                float wh2 = wh * wh;
                rd += es; r1 += wh; r2 = fmaf(wh2, s, r2);
                cd[e] += es; c1v[e] += wh; c2v[e] = fmaf(wh2, s, c2v[e]);
            }
        }

        // row reduce across 16 lanes (both rh halves in parallel; xor<16 keeps bit4)
        #pragma unroll
        for (int o = 1; o <= 8; o <<= 1) {
            rd += __shfl_xor_sync(0xffffffffu, rd, o);
            r1 += __shfl_xor_sync(0xffffffffu, r1, o);
            r2 += __shfl_xor_sync(0xffffffffu, r2, o);
        }
        if (cl == 0) { rowacc[0][row] = rd; rowacc[1][row] = r1; rowacc[2][row] = r2; }
    }

    // col side: merge rh halves, then stash per-warp
    #pragma unroll
    for (int e = 0; e < 8; e++) {
        cd[e]  += __shfl_xor_sync(0xffffffffu, cd[e],  16);
        c1v[e] += __shfl_xor_sync(0xffffffffu, c1v[e], 16);
        c2v[e] += __shfl_xor_sync(0xffffffffu, c2v[e], 16);
    }
    if (rh == 0) {
        #pragma unroll
        for (int e = 0; e < 8; e++) {
            int col = cl * 8 + e;
            colacc[w][0][col] = cd[e];
            colacc[w][1][col] = c1v[e];
            colacc[w][2][col] = c2v[e];
        }
    }
    __syncthreads();

    if (tid < 128) {
        int row = tid, ig = by * 128 + row;
        #pragma unroll
        for (int k = 0; k < 3; k++)
            g_pdr[k][bx][ig] = rowacc[k][row];
    } else if (tid < 256) {
        int col = tid - 128, jg = bx * 128 + col;
        #pragma unroll
        for (int k = 0; k < 3; k++) {
            float v = 0.0f;
            #pragma unroll
            for (int ww = 0; ww < 16; ww++) v += colacc[ww][k][col];
            g_pdc[k][by][jg] = diag ? 0.0f : v;
        }
    }
}

// ---------------- kernel 5: reduce valid partial slots per row --------------
__global__ void rowred_kernel() {
    int i = blockIdx.x * blockDim.x + threadIdx.x;
    int p = i >> 7;
    float d = 0.0f, a = 0.0f, b = 0.0f;
    for (int s = p; s < NT; s++) {
        d += g_pdr[0][s][i];
        a += g_pdr[1][s][i];
        b += g_pdr[2][s][i];
    }
    for (int s = 0; s <= p; s++) {
        d += g_pdc[0][s][i];
        a += g_pdc[1][s][i];
        b += g_pdc[2][s][i];
    }
    b *= INV_T;                              // deferred 1/T on S2
    float L = logf(d + EPSV);
    g_row[i] = (b - a * L) / (a + EPSV);
}

// ---------------- kernel 6: final mean ----------------
__global__ void final_kernel(float* __restrict__ out) {
    __shared__ float smem[32];
    int tid = threadIdx.x;
    float s = 0.0f;
    for (int i = tid; i < Nn; i += 1024) s += g_row[i];
    #pragma unroll
    for (int off = 16; off; off >>= 1) s += __shfl_xor_sync(0xffffffffu, s, off);
    int lane = tid & 31, w = tid >> 5;
    if (lane == 0) smem[w] = s;
    __syncthreads();
    if (tid == 0) {
        float t = 0.0f;
        #pragma unroll
        for (int x = 0; x < 32; x++) t += smem[x];
        out[0] = -(t / (float)Nn);
    }
}

// ---------------- launch ----------------
extern "C" void kernel_launch(void* const* d_in, const int* in_sizes, int n_in,
                              void* d_out, int out_size) {
    const float* feats  = (const float*)d_in[0];
    const float* labels = (const float*)d_in[1];
    float* out = (float*)d_out;

    cudaFuncSetAttribute(simgen_kernel, cudaFuncAttributeMaxDynamicSharedMemorySize, PANEL_BYTES);

    labels_kernel<<<1, 1024>>>(labels);
    normalize_kernel<<<512, 256>>>(feats);
    simgen_kernel<<<GRID2, 512, PANEL_BYTES>>>();
    epiflat_kernel<<<NTILES, 512>>>(labels);
    rowred_kernel<<<16, 256>>>();
    final_kernel<<<1, 1024>>>(out);
}

// round 9
// speedup vs baseline: 1.0555x; 1.0555x over previous
#include <cuda_runtime.h>
#include <cuda_bf16.h>
#include <math.h>
#include <stdint.h>

#define Nn   4096
#define Bb   2048
#define DIM  128
#define NT   32
#define NTILES 528
#define GRID2 132                       // 132 CTAs x exactly 4 tiles
#define EPSV 1e-8f
#define INV_T 14.285714285714285714f   // 1/0.07
#define LOG2E 1.44269504088896340736f

// ---------------- static device scratch ----------------
__device__ __nv_bfloat16 g_zh[Nn * DIM];          // 1 MB hi split
__device__ __nv_bfloat16 g_zl[Nn * DIM];          // 1 MB lo split
__device__ float         g_simu[(size_t)NTILES * 16384]; // 34.6 MB upper-tri tiles
__device__ float         g_pdr[3][NT][Nn];        // row-side partials (slot = bx)
__device__ float         g_pdc[3][NT][Nn];        // col-side partials (slot = by)
__device__ float         g_row[Nn];
__device__ float         g_inv_dymax;
__device__ unsigned      g_min_key;

// panel layout in dynamic smem (bf16, 128 rows x 136 stride = 272 B/row)
#define PSTRIDE_B 272
#define OFF_A_H   0
#define OFF_A_L   34816
#define OFF_B0_H  69632
#define OFF_B0_L  104448
#define OFF_B1_H  139264
#define OFF_B1_L  174080
#define PANEL_BYTES 208896

__device__ __forceinline__ unsigned fflip(float f) {
    unsigned u = __float_as_uint(f);
    return (u & 0x80000000u) ? ~u : (u | 0x80000000u);
}
__device__ __forceinline__ float funflip(unsigned k) {
    return __uint_as_float((k & 0x80000000u) ? (k & 0x7FFFFFFFu) : ~k);
}
__device__ __forceinline__ uint32_t smem_u32(const void* p) {
    uint32_t a;
    asm("{ .reg .u64 t; cvta.to.shared.u64 t, %1; cvt.u32.u64 %0, t; }" : "=r"(a) : "l"(p));
    return a;
}
__device__ __forceinline__ void cp16(uint32_t s, const void* g) {
    asm volatile("cp.async.cg.shared.global [%0], [%1], 16;" :: "r"(s), "l"(g));
}
__device__ __forceinline__ void cp_commit() {
    asm volatile("cp.async.commit_group;");
}
template <int N> __device__ __forceinline__ void cp_wait() {
    asm volatile("cp.async.wait_group %0;" :: "n"(N));
}
__device__ __forceinline__ void ldsm4(uint32_t& r0, uint32_t& r1, uint32_t& r2, uint32_t& r3, uint32_t a) {
    asm volatile("ldmatrix.sync.aligned.m8n8.x4.shared.b16 {%0,%1,%2,%3}, [%4];"
                 : "=r"(r0), "=r"(r1), "=r"(r2), "=r"(r3) : "r"(a));
}
__device__ __forceinline__ void mma16816(float* c, const uint32_t* a, const uint32_t* b) {
    asm volatile("mma.sync.aligned.m16n8k16.row.col.f32.bf16.bf16.f32 "
                 "{%0,%1,%2,%3},{%4,%5,%6,%7},{%8,%9},{%0,%1,%2,%3};"
                 : "+f"(c[0]), "+f"(c[1]), "+f"(c[2]), "+f"(c[3])
                 : "r"(a[0]), "r"(a[1]), "r"(a[2]), "r"(a[3]), "r"(b[0]), "r"(b[1]));
}

// ---------------- kernel 1: labels min/max + init ----------------
__global__ void labels_kernel(const float* __restrict__ labels) {
    __shared__ float smn[32], smx[32];
    int tid = threadIdx.x;
    float mn = 1e30f, mx = -1e30f;
    for (int i = tid; i < Bb; i += 1024) {
        float v = labels[i];
        mn = fminf(mn, v); mx = fmaxf(mx, v);
    }
    #pragma unroll
    for (int off = 16; off; off >>= 1) {
        mn = fminf(mn, __shfl_xor_sync(0xffffffffu, mn, off));
        mx = fmaxf(mx, __shfl_xor_sync(0xffffffffu, mx, off));
    }
    int lane = tid & 31, w = tid >> 5;
    if (lane == 0) { smn[w] = mn; smx[w] = mx; }
    __syncthreads();
    if (tid == 0) {
        float a = smn[0], b = smx[0];
        for (int i = 1; i < 32; i++) { a = fminf(a, smn[i]); b = fmaxf(b, smx[i]); }
        g_inv_dymax = 1.0f / ((b - a) + EPSV);
        g_min_key   = 0xFFFFFFFFu;
    }
}

// ---------------- kernel 2: normalize + bf16 split ----------------
__global__ void normalize_kernel(const float* __restrict__ feats) {
    int gw   = (blockIdx.x * blockDim.x + threadIdx.x) >> 5;
    int lane = threadIdx.x & 31;
    if (gw >= Nn) return;
    int b = gw & (Bb - 1);
    int v = gw >> 11;
    const float* src = feats + ((size_t)b * 2 + v) * DIM;
    float4 x = *(const float4*)(src + lane * 4);
    float s = x.x * x.x + x.y * x.y + x.z * x.z + x.w * x.w;
    #pragma unroll
    for (int off = 16; off; off >>= 1) s += __shfl_xor_sync(0xffffffffu, s, off);
    float inv = 1.0f / fmaxf(sqrtf(s), 1e-12f);
    float f0 = x.x * inv, f1 = x.y * inv, f2 = x.z * inv, f3 = x.w * inv;
    __nv_bfloat16 h0 = __float2bfloat16(f0), h1 = __float2bfloat16(f1);
    __nv_bfloat16 h2 = __float2bfloat16(f2), h3 = __float2bfloat16(f3);
    __nv_bfloat16 l0 = __float2bfloat16(f0 - __bfloat162float(h0));
    __nv_bfloat16 l1 = __float2bfloat16(f1 - __bfloat162float(h1));
    __nv_bfloat16 l2 = __float2bfloat16(f2 - __bfloat162float(h2));
    __nv_bfloat16 l3 = __float2bfloat16(f3 - __bfloat162float(h3));
    size_t base = (size_t)gw * DIM + lane * 4;
    *(__nv_bfloat162*)(g_zh + base)     = __halves2bfloat162(h0, h1);
    *(__nv_bfloat162*)(g_zh + base + 2) = __halves2bfloat162(h2, h3);
    *(__nv_bfloat162*)(g_zl + base)     = __halves2bfloat162(l0, l1);
    *(__nv_bfloat162*)(g_zl + base + 2) = __halves2bfloat162(l2, l3);
}

// ---- cp.async panel loaders (H+L pair for one 128-row block), 512 threads --
__device__ __forceinline__ void load_panels(uint32_t sb, uint32_t offH, uint32_t offL,
                                            int blk, int tid) {
    #pragma unroll
    for (int c = tid; c < 2048; c += 512) {
        int row = c >> 4, ch = c & 15;
        uint32_t so = (uint32_t)row * PSTRIDE_B + ch * 16;
        size_t go = (size_t)(blk * 128 + row) * DIM + ch * 8;
        cp16(sb + offH + so, g_zh + go);
        cp16(sb + offL + so, g_zl + go);
    }
}

// ---- MMA on current buffers (16 warps, 32x32 outputs each) ----
__device__ __forceinline__ void tile_mma(uint32_t sb, uint32_t offBH, uint32_t offBL,
                                         int wm, int wn, int lane, float c[2][4][4]) {
    #pragma unroll
    for (int im = 0; im < 2; im++)
        #pragma unroll
        for (int in = 0; in < 4; in++)
            #pragma unroll
            for (int r = 0; r < 4; r++) c[im][in][r] = 0.0f;

    int a_row  = lane & 15;
    int a_koff = (lane >> 4) * 8;
    int b_row  = ((lane >> 4) & 1) * 8 + (lane & 7);
    int b_koff = ((lane >> 3) & 1) * 8;

    #pragma unroll
    for (int kc = 0; kc < 8; kc++) {
        uint32_t ah[2][4], al[2][4], bh[4][2], bl[4][2];
        #pragma unroll
        for (int im = 0; im < 2; im++) {
            uint32_t off = (uint32_t)(wm * 32 + im * 16 + a_row) * PSTRIDE_B
                         + (kc * 16 + a_koff) * 2;
            ldsm4(ah[im][0], ah[im][1], ah[im][2], ah[im][3], sb + OFF_A_H + off);
            ldsm4(al[im][0], al[im][1], al[im][2], al[im][3], sb + OFF_A_L + off);
        }
        #pragma unroll
        for (int p = 0; p < 2; p++) {
            uint32_t off = (uint32_t)(wn * 32 + p * 16 + b_row) * PSTRIDE_B
                         + (kc * 16 + b_koff) * 2;
            ldsm4(bh[2*p][0], bh[2*p][1], bh[2*p+1][0], bh[2*p+1][1], sb + offBH + off);
            ldsm4(bl[2*p][0], bl[2*p][1], bl[2*p+1][0], bl[2*p+1][1], sb + offBL + off);
        }
        #pragma unroll
        for (int im = 0; im < 2; im++)
            #pragma unroll
            for (int in = 0; in < 4; in++) {
                mma16816(c[im][in], ah[im], bh[in]);
                mma16816(c[im][in], ah[im], bl[in]);
                mma16816(c[im][in], al[im], bh[in]);
            }
    }
}

// ---------------- kernel 3: persistent pipelined GEMM (132 x 4 tiles) -------
__global__ void __launch_bounds__(512, 1) simgen_kernel() {
    extern __shared__ char sm[];
    __shared__ float wmin[16];
    uint32_t sb = smem_u32(sm);
    int tid = threadIdx.x, wid = tid >> 5, lane = tid & 31;
    int wm = wid & 3, wn = wid >> 2;
    int tr = lane >> 2, tq = (lane & 3) * 2;

    int ts = blockIdx.x * 4;
    int te = ts + 4;

    int by = 0, off = 0;
    while (ts >= off + (NT - by)) { off += (NT - by); by++; }
    int bx = by + (ts - off);

    float mymin = 1e30f;
    int t = ts;
    while (t < te) {
        int nb = NT - bx;
        if (nb > te - t) nb = te - t;

        load_panels(sb, OFF_A_H, OFF_A_L, by, tid);
        load_panels(sb, OFF_B0_H, OFF_B0_L, bx, tid);
        cp_commit();

        for (int j = 0; j < nb; j++) {
            uint32_t bH = (j & 1) ? OFF_B1_H : OFF_B0_H;
            uint32_t bL = (j & 1) ? OFF_B1_L : OFF_B0_L;
            if (j + 1 < nb) {
                load_panels(sb, (j & 1) ? OFF_B0_H : OFF_B1_H,
                                (j & 1) ? OFF_B0_L : OFF_B1_L, bx + j + 1, tid);
                cp_commit();
                cp_wait<1>();
            } else {
                cp_wait<0>();
            }
            __syncthreads();

            float c[2][4][4];
            tile_mma(sb, bH, bL, wm, wn, lane, c);

            float* dst = g_simu + (size_t)(t + j) * 16384;
            #pragma unroll
            for (int im = 0; im < 2; im++)
                #pragma unroll
                for (int in = 0; in < 4; in++) {
                    int rl = wm * 32 + im * 16 + tr;
                    int cl = wn * 32 + in * 8 + tq;
                    float2 v0 = make_float2(c[im][in][0], c[im][in][1]);
                    float2 v1 = make_float2(c[im][in][2], c[im][in][3]);
                    *(float2*)(dst + rl * 128 + cl)       = v0;
                    *(float2*)(dst + (rl + 8) * 128 + cl) = v1;
                    mymin = fminf(mymin, fminf(fminf(v0.x, v0.y), fminf(v1.x, v1.y)));
                }
            __syncthreads();
        }
        t += nb;
        bx += nb;
        if (bx >= NT) { by++; bx = by; }
    }

    #pragma unroll
    for (int o = 16; o; o >>= 1) mymin = fminf(mymin, __shfl_xor_sync(0xffffffffu, mymin, o));
    if (lane == 0) wmin[wid] = mymin;
    __syncthreads();
    if (tid == 0) {
        float m = wmin[0];
        #pragma unroll
        for (int w = 1; w < 16; w++) m = fminf(m, wmin[w]);
        atomicMin(&g_min_key, fflip(m));
    }
}

// ---------------- kernel 4: flat dual-sided epilogue ----------------
// 512 threads, 16 warps; warp handles row = it*16+w, lane l handles cols 4l..4l+3.
// Row reduce: 3 shfl levels -> 4 smem group slots, finished by writer phase.
__global__ void __launch_bounds__(512, 2) epiflat_kernel(const float* __restrict__ labels) {
    __shared__ float yr[128], yc[128];
    __shared__ float rowacc[3][4][128];
    __shared__ float colacc[16][3][128];
    int tid = threadIdx.x, w = tid >> 5, l = tid & 31;

    int t = blockIdx.x;
    int by = 0, off = 0;
    while (t >= off + (NT - by)) { off += (NT - by); by++; }
    int bx = by + (t - off);
    bool diag = (by == bx);

    for (int i = tid; i < 128; i += 512) {
        yr[i] = labels[(by * 128 + i) & (Bb - 1)];
        yc[i] = labels[(bx * 128 + i) & (Bb - 1)];
    }
    __syncthreads();

    float inv_dz = 1.0f / ((1.0f - funflip(g_min_key)) + EPSV);
    float inv_dy = g_inv_dymax;
    const float K1 = INV_T * LOG2E;        // exp(s/T) = exp2(s*K1)
    const float K2 = -2.0f * LOG2E;        // exp(-2dy^2) = exp2(dy*dy*K2)
    const float4* tp = (const float4*)(g_simu + (size_t)t * 16384);

    float yj[4];
    #pragma unroll
    for (int e = 0; e < 4; e++) yj[e] = yc[4 * l + e];

    float cd[4] = {0,0,0,0}, c1v[4] = {0,0,0,0}, c2v[4] = {0,0,0,0};

    #pragma unroll
    for (int it = 0; it < 8; it++) {
        int row = it * 16 + w;
        float4 s4 = tp[row * 32 + l];
        float se[4] = {s4.x, s4.y, s4.z, s4.w};
        float yi = yr[row];
        float rd = 0.0f, r1 = 0.0f, r2 = 0.0f;

        if (!diag) {
            #pragma unroll
            for (int e = 0; e < 4; e++) {
                float s   = se[e];
                float es  = exp2f(s * K1);
                float dy  = yi - yj[e];
                float wk  = exp2f(dy * (dy * K2));
                float u   = fmaf(-s, inv_dz, fmaf(-fabsf(dy), inv_dy, inv_dz));
                float wh  = fmaf(wk, u, 1.0f + fmaxf(-u, 0.0f));
                float wh2 = wh * wh;
                rd += es; r1 += wh; r2 = fmaf(wh2, s, r2);
                cd[e] += es; c1v[e] += wh; c2v[e] = fmaf(wh2, s, c2v[e]);
            }
        } else {
            #pragma unroll
            for (int e = 0; e < 4; e++) {
                float s   = se[e];
                float es  = exp2f(s * K1);
                float dy  = yi - yj[e];
                float wk  = exp2f(dy * (dy * K2));
                float u   = fmaf(-s, inv_dz, fmaf(-fabsf(dy), inv_dy, inv_dz));
                float wh  = fmaf(wk, u, 1.0f + fmaxf(-u, 0.0f));
                if (row == 4 * l + e) { es = 0.0f; wh = 0.0f; }
                float wh2 = wh * wh;
                rd += es; r1 += wh; r2 = fmaf(wh2, s, r2);
                cd[e] += es; c1v[e] += wh; c2v[e] = fmaf(wh2, s, c2v[e]);
            }
        }

        // partial row reduce: 3 levels -> sums over 8-lane groups (32 cols each)
        #pragma unroll
        for (int o = 1; o <= 4; o <<= 1) {
            rd += __shfl_xor_sync(0xffffffffu, rd, o);
            r1 += __shfl_xor_sync(0xffffffffu, r1, o);
            r2 += __shfl_xor_sync(0xffffffffu, r2, o);
        }
        if ((l & 7) == 0) {
            int g = l >> 3;
            rowacc[0][g][row] = rd;
            rowacc[1][g][row] = r1;
            rowacc[2][g][row] = r2;
        }
    }

    #pragma unroll
    for (int e = 0; e < 4; e++) {
        colacc[w][0][4 * l + e] = cd[e];
        colacc[w][1][4 * l + e] = c1v[e];
        colacc[w][2][4 * l + e] = c2v[e];
    }
    __syncthreads();

    if (tid < 128) {
        int row = tid, ig = by * 128 + row;
        #pragma unroll
        for (int k = 0; k < 3; k++)
            g_pdr[k][bx][ig] = (rowacc[k][0][row] + rowacc[k][1][row])
                             + (rowacc[k][2][row] + rowacc[k][3][row]);
    } else if (tid < 256) {
        int col = tid - 128, jg = bx * 128 + col;
        #pragma unroll
        for (int k = 0; k < 3; k++) {
            float v = 0.0f;
            #pragma unroll
            for (int ww = 0; ww < 16; ww++) v += colacc[ww][k][col];
            g_pdc[k][by][jg] = diag ? 0.0f : v;
        }
    }
}

// ---------------- kernel 5: reduce valid partial slots per row --------------
__global__ void rowred_kernel() {
    int i = blockIdx.x * blockDim.x + threadIdx.x;
    int p = i >> 7;
    float d = 0.0f, a = 0.0f, b = 0.0f;
    for (int s = p; s < NT; s++) {
        d += g_pdr[0][s][i];
        a += g_pdr[1][s][i];
        b += g_pdr[2][s][i];
    }
    for (int s = 0; s <= p; s++) {
        d += g_pdc[0][s][i];
        a += g_pdc[1][s][i];
        b += g_pdc[2][s][i];
    }
    b *= INV_T;                              // deferred 1/T on S2
    float L = logf(d + EPSV);
    g_row[i] = (b - a * L) / (a + EPSV);
}

// ---------------- kernel 6: final mean ----------------
__global__ void final_kernel(float* __restrict__ out) {
    __shared__ float smem[32];
    int tid = threadIdx.x;
    float s = 0.0f;
    for (int i = tid; i < Nn; i += 1024) s += g_row[i];
    #pragma unroll
    for (int off = 16; off; off >>= 1) s += __shfl_xor_sync(0xffffffffu, s, off);
    int lane = tid & 31, w = tid >> 5;
    if (lane == 0) smem[w] = s;
    __syncthreads();
    if (tid == 0) {
        float t = 0.0f;
        #pragma unroll
        for (int x = 0; x < 32; x++) t += smem[x];
        out[0] = -(t / (float)Nn);
    }
}

// ---------------- launch ----------------
extern "C" void kernel_launch(void* const* d_in, const int* in_sizes, int n_in,
                              void* d_out, int out_size) {
    const float* feats  = (const float*)d_in[0];
    const float* labels = (const float*)d_in[1];
    float* out = (float*)d_out;

    cudaFuncSetAttribute(simgen_kernel, cudaFuncAttributeMaxDynamicSharedMemorySize, PANEL_BYTES);

    labels_kernel<<<1, 1024>>>(labels);
    normalize_kernel<<<512, 256>>>(feats);
    simgen_kernel<<<GRID2, 512, PANEL_BYTES>>>();
    epiflat_kernel<<<NTILES, 512>>>(labels);
    rowred_kernel<<<16, 256>>>();
    final_kernel<<<1, 1024>>>(out);
}